// round 9
// baseline (speedup 1.0000x reference)
#include <cuda_runtime.h>
#include <cstdint>

// ---------------------------------------------------------------------------
// Problem constants
// ---------------------------------------------------------------------------
#define BB 64
#define CC 3
#define HH 384
#define WW 384
#define HW (HH * WW)            // 147456
#define CHW (CC * HW)           // 442368
#define NTOT (BB * CHW)         // 28311552
// 32 floats (128B) per thread; W % 32 == 0 so a chunk never straddles a row
#define CPR  (WW / 32)          // chunks per row      = 12
#define CPC  (HW / 32)          // chunks per channel  = 4608
#define CPI  (CHW / 32)         // chunks per image    = 13824
#define NCH  (NTOT / 32)        // total chunks        = 884736
#define BLK  256
#define NBLK (NCH / BLK)        // 3456 blocks, exact
#define BLOCKS_PER_IMG (CPI / BLK)   // 54, exact -> one image per block

// ---------------------------------------------------------------------------
// constexpr threefry2x32 (JAX schedule) — compile-time child keys of
// jax.random.split(jax.random.key(42), 6), partitionable: child i = tf(k,0,i)
// ---------------------------------------------------------------------------
constexpr unsigned long long tf_pair_ce(unsigned k0, unsigned k1,
                                        unsigned x0, unsigned x1) {
    unsigned k2 = k0 ^ k1 ^ 0x1BD11BDAu;
    x0 += k0; x1 += k1;
    const int rots[5][4] = {{13,15,26,6},{17,29,16,24},{13,15,26,6},
                            {17,29,16,24},{13,15,26,6}};
    const unsigned ka[5] = {k1, k2, k0, k1, k2};
    const unsigned kb[5] = {k2, k0, k1, k2, k0};
    for (int g = 0; g < 5; ++g) {
        for (int j = 0; j < 4; ++j) {
            x0 += x1;
            int r = rots[g][j];
            x1 = (x1 << r) | (x1 >> (32 - r));
            x1 ^= x0;
        }
        x0 += ka[g];
        x1 += kb[g] + (unsigned)(g + 1);
    }
    return ((unsigned long long)x0 << 32) | (unsigned long long)x1;
}

constexpr unsigned long long KP_ = tf_pair_ce(0u, 42u, 0u, 0u);
constexpr unsigned long long KA_ = tf_pair_ce(0u, 42u, 0u, 1u);
constexpr unsigned long long KR_ = tf_pair_ce(0u, 42u, 0u, 2u);
constexpr unsigned long long KT_ = tf_pair_ce(0u, 42u, 0u, 3u);
constexpr unsigned long long KL_ = tf_pair_ce(0u, 42u, 0u, 4u);
constexpr unsigned long long KN_ = tf_pair_ce(0u, 42u, 0u, 5u);

#define KHI(k) ((unsigned)((k) >> 32))
#define KLO(k) ((unsigned)((k) & 0xFFFFFFFFull))

// ---------------------------------------------------------------------------
// Device threefry: bits(i) = out0 ^ out1 of threefry(key, 0, i)
// ---------------------------------------------------------------------------
__device__ __forceinline__ unsigned tf_bits(unsigned k0, unsigned k1, unsigned ctr) {
    unsigned k2 = k0 ^ k1 ^ 0x1BD11BDAu;
    unsigned x0 = k0;
    unsigned x1 = ctr + k1;
#define TFR(r) { x0 += x1; x1 = __funnelshift_l(x1, x1, (r)); x1 ^= x0; }
    TFR(13) TFR(15) TFR(26) TFR(6)
    x0 += k1; x1 += k2 + 1u;
    TFR(17) TFR(29) TFR(16) TFR(24)
    x0 += k2; x1 += k0 + 2u;
    TFR(13) TFR(15) TFR(26) TFR(6)
    x0 += k0; x1 += k1 + 3u;
    TFR(17) TFR(29) TFR(16) TFR(24)
    x0 += k1; x1 += k2 + 4u;
    TFR(13) TFR(15) TFR(26) TFR(6)
    x0 += k2; x1 += k0 + 5u;
#undef TFR
    return x0 ^ x1;
}

__device__ __forceinline__ float u01(unsigned bits) {
    return __uint_as_float((bits >> 9) | 0x3F800000u) - 1.0f;
}

// ---------------------------------------------------------------------------
// Per-sample erase rectangle {top, bottom, left, right}; empty when invalid.
// Recomputed per-block (each block covers exactly one image) — exactly the
// same arithmetic as the reference, so bit-identical decisions.
// ---------------------------------------------------------------------------
__device__ __forceinline__ int4 compute_rect(int b) {
    float up = u01(tf_bits(KHI(KP_), KLO(KP_), (unsigned)b));
    bool apply = (up <= 0.5f);

    float ua = u01(tf_bits(KHI(KA_), KLO(KA_), (unsigned)b));
    const float RA = 0.33f - 0.02f;
    float ta_u = fmaxf(0.02f, __fadd_rn(__fmul_rn(ua, RA), 0.02f));
    float ta = __fmul_rn(ta_u, 147456.0f);

    float ur = u01(tf_bits(KHI(KR_), KLO(KR_), (unsigned)b));
    const float RR = 3.3f - 0.3f;
    float ar = fmaxf(0.3f, __fadd_rn(__fmul_rn(ur, RR), 0.3f));

    int h_e = (int)rintf(__fsqrt_rn(__fmul_rn(ta, ar)));
    int w_e = (int)rintf(__fsqrt_rn(__fdiv_rn(ta, ar)));

    bool valid = apply && (h_e < HH) && (w_e < WW);

    float ut = u01(tf_bits(KHI(KT_), KLO(KT_), (unsigned)b));
    float ul = u01(tf_bits(KHI(KL_), KLO(KL_), (unsigned)b));
    int top  = (int)floorf(__fmul_rn(ut, (float)(HH - h_e + 1)));
    int left = (int)floorf(__fmul_rn(ul, (float)(WW - w_e + 1)));

    int4 r;
    if (valid) { r.x = top; r.y = top + h_e; r.z = left; r.w = left + w_e; }
    else       { r.x = 0;   r.y = 0;         r.z = 0;    r.w = 0; }
    return r;
}

// ---------------------------------------------------------------------------
// Noise at global element index i (JAX normal = sqrt(2)*erfinv(uniform(-1,1)))
// ---------------------------------------------------------------------------
__device__ __forceinline__ float noise_at(unsigned i) {
    unsigned bits = tf_bits(KHI(KN_), KLO(KN_), i);
    float u = u01(bits);
    const float LO = -0.99999994039535522461f;    // nextafter(-1,0) f32
    float v = fmaxf(LO, __fadd_rn(__fmul_rn(u, 2.0f), LO));
    return __uint_as_float(0x3FB504F3u) * erfinvf(v);
}

// ---------------------------------------------------------------------------
// Single fused streaming kernel: 32 contiguous floats (8x float4) per thread.
// A 32-float aligned chunk lies entirely within one (b, c, h) row, and each
// 256-thread block lies entirely within one image b.
// ---------------------------------------------------------------------------
__global__ void __launch_bounds__(BLK)
erase_kernel(const float4* __restrict__ x,
             const float* __restrict__ mean,
             const float* __restrict__ stdv,
             float4* __restrict__ out) {
    __shared__ int4 s_rect;

    int t = blockIdx.x * BLK + threadIdx.x;      // chunk id, < NCH
    int b = blockIdx.x / BLOCKS_PER_IMG;         // image id (uniform per block)

    if (threadIdx.x == 0) s_rect = compute_rect(b);

    // decode chunk -> (c, h, w0) once per thread (b already known)
    int r0 = t - b * CPI;
    int c  = r0 / CPC;
    int r1 = r0 - c * CPC;
    int h  = r1 / CPR;
    int w0 = (r1 - h * CPR) << 5;                // starting w of this chunk

    // front-batch 8 vector loads for MLP=8 (streaming: no reuse, evict-first)
    alignas(16) float o[32];
    float4* ov4 = reinterpret_cast<float4*>(o);
    const float4* xp = x + (size_t)t * 8;
    #pragma unroll
    for (int q = 0; q < 8; ++q)
        ov4[q] = __ldcs(xp + q);

    float inv  = 1.0f / __ldg(&stdv[c]);
    float bias = -__ldg(&mean[c]) * inv;

    #pragma unroll
    for (int j = 0; j < 32; ++j)
        o[j] = fmaf(o[j], inv, bias);

    __syncthreads();                             // s_rect ready
    int4 rc = s_rect;

    // row-range + column-overlap test once per thread; rare path per-lane
    if (h >= rc.x && h < rc.y && w0 + 31 >= rc.z && w0 < rc.w) {
        unsigned i0 = (unsigned)t * 32u;         // global element index
        #pragma unroll
        for (int j = 0; j < 32; ++j) {
            int w = w0 + j;
            if (w >= rc.z && w < rc.w) o[j] = noise_at(i0 + (unsigned)j);
        }
    }

    float4* op = out + (size_t)t * 8;
    #pragma unroll
    for (int q = 0; q < 8; ++q)
        __stcs(op + q, ov4[q]);
}

// ---------------------------------------------------------------------------
// Launch
// ---------------------------------------------------------------------------
extern "C" void kernel_launch(void* const* d_in, const int* in_sizes, int n_in,
                              void* d_out, int out_size) {
    const float4* x   = (const float4*)d_in[0];
    const float*  mn  = (const float*)d_in[1];
    const float*  sd  = (const float*)d_in[2];
    float4*       out = (float4*)d_out;

    erase_kernel<<<NBLK, BLK>>>(x, mn, sd, out);
}

// round 10
// speedup vs baseline: 1.3558x; 1.3558x over previous
#include <cuda_runtime.h>
#include <cstdint>

// ---------------------------------------------------------------------------
// Problem constants
// ---------------------------------------------------------------------------
#define BB 64
#define CC 3
#define HH 384
#define WW 384
#define HW (HH * WW)            // 147456
#define CHW (CC * HW)           // 442368
#define NTOT (BB * CHW)         // 28311552
// 16 floats (64B) per thread; W % 16 == 0 so a chunk never straddles a row
#define CPR  (WW / 16)          // chunks per row      = 24
#define CPC  (HW / 16)          // chunks per channel  = 9216
#define CPI  (CHW / 16)         // chunks per image    = 27648
#define NCH  (NTOT / 16)        // total chunks        = 1769472
#define BLK  256
#define NBLK (NCH / BLK)        // 6912 blocks, exact
#define BLOCKS_PER_IMG (CPI / BLK)   // 108, exact -> one image per block

// ---------------------------------------------------------------------------
// constexpr threefry2x32 (JAX schedule) — compile-time child keys of
// jax.random.split(jax.random.key(42), 6), partitionable: child i = tf(k,0,i)
// ---------------------------------------------------------------------------
constexpr unsigned long long tf_pair_ce(unsigned k0, unsigned k1,
                                        unsigned x0, unsigned x1) {
    unsigned k2 = k0 ^ k1 ^ 0x1BD11BDAu;
    x0 += k0; x1 += k1;
    const int rots[5][4] = {{13,15,26,6},{17,29,16,24},{13,15,26,6},
                            {17,29,16,24},{13,15,26,6}};
    const unsigned ka[5] = {k1, k2, k0, k1, k2};
    const unsigned kb[5] = {k2, k0, k1, k2, k0};
    for (int g = 0; g < 5; ++g) {
        for (int j = 0; j < 4; ++j) {
            x0 += x1;
            int r = rots[g][j];
            x1 = (x1 << r) | (x1 >> (32 - r));
            x1 ^= x0;
        }
        x0 += ka[g];
        x1 += kb[g] + (unsigned)(g + 1);
    }
    return ((unsigned long long)x0 << 32) | (unsigned long long)x1;
}

constexpr unsigned long long KP_ = tf_pair_ce(0u, 42u, 0u, 0u);
constexpr unsigned long long KA_ = tf_pair_ce(0u, 42u, 0u, 1u);
constexpr unsigned long long KR_ = tf_pair_ce(0u, 42u, 0u, 2u);
constexpr unsigned long long KT_ = tf_pair_ce(0u, 42u, 0u, 3u);
constexpr unsigned long long KL_ = tf_pair_ce(0u, 42u, 0u, 4u);
constexpr unsigned long long KN_ = tf_pair_ce(0u, 42u, 0u, 5u);

#define KHI(k) ((unsigned)((k) >> 32))
#define KLO(k) ((unsigned)((k) & 0xFFFFFFFFull))

// ---------------------------------------------------------------------------
// Device threefry: bits(i) = out0 ^ out1 of threefry(key, 0, i)
// ---------------------------------------------------------------------------
__device__ __forceinline__ unsigned tf_bits(unsigned k0, unsigned k1, unsigned ctr) {
    unsigned k2 = k0 ^ k1 ^ 0x1BD11BDAu;
    unsigned x0 = k0;
    unsigned x1 = ctr + k1;
#define TFR(r) { x0 += x1; x1 = __funnelshift_l(x1, x1, (r)); x1 ^= x0; }
    TFR(13) TFR(15) TFR(26) TFR(6)
    x0 += k1; x1 += k2 + 1u;
    TFR(17) TFR(29) TFR(16) TFR(24)
    x0 += k2; x1 += k0 + 2u;
    TFR(13) TFR(15) TFR(26) TFR(6)
    x0 += k0; x1 += k1 + 3u;
    TFR(17) TFR(29) TFR(16) TFR(24)
    x0 += k1; x1 += k2 + 4u;
    TFR(13) TFR(15) TFR(26) TFR(6)
    x0 += k2; x1 += k0 + 5u;
#undef TFR
    return x0 ^ x1;
}

__device__ __forceinline__ float u01(unsigned bits) {
    return __uint_as_float((bits >> 9) | 0x3F800000u) - 1.0f;
}

// ---------------------------------------------------------------------------
// Per-sample erase rectangle {top, bottom, left, right}; empty when invalid.
// Recomputed once per block (each block covers exactly one image) — exactly
// the same arithmetic as the reference, so bit-identical decisions.
// ---------------------------------------------------------------------------
__device__ __forceinline__ int4 compute_rect(int b) {
    float up = u01(tf_bits(KHI(KP_), KLO(KP_), (unsigned)b));
    bool apply = (up <= 0.5f);

    float ua = u01(tf_bits(KHI(KA_), KLO(KA_), (unsigned)b));
    const float RA = 0.33f - 0.02f;
    float ta_u = fmaxf(0.02f, __fadd_rn(__fmul_rn(ua, RA), 0.02f));
    float ta = __fmul_rn(ta_u, 147456.0f);

    float ur = u01(tf_bits(KHI(KR_), KLO(KR_), (unsigned)b));
    const float RR = 3.3f - 0.3f;
    float ar = fmaxf(0.3f, __fadd_rn(__fmul_rn(ur, RR), 0.3f));

    int h_e = (int)rintf(__fsqrt_rn(__fmul_rn(ta, ar)));
    int w_e = (int)rintf(__fsqrt_rn(__fdiv_rn(ta, ar)));

    bool valid = apply && (h_e < HH) && (w_e < WW);

    float ut = u01(tf_bits(KHI(KT_), KLO(KT_), (unsigned)b));
    float ul = u01(tf_bits(KHI(KL_), KLO(KL_), (unsigned)b));
    int top  = (int)floorf(__fmul_rn(ut, (float)(HH - h_e + 1)));
    int left = (int)floorf(__fmul_rn(ul, (float)(WW - w_e + 1)));

    int4 r;
    if (valid) { r.x = top; r.y = top + h_e; r.z = left; r.w = left + w_e; }
    else       { r.x = 0;   r.y = 0;         r.z = 0;    r.w = 0; }
    return r;
}

// ---------------------------------------------------------------------------
// Noise at global element index i (JAX normal = sqrt(2)*erfinv(uniform(-1,1)))
// ---------------------------------------------------------------------------
__device__ __forceinline__ float noise_at(unsigned i) {
    unsigned bits = tf_bits(KHI(KN_), KLO(KN_), i);
    float u = u01(bits);
    const float LO = -0.99999994039535522461f;    // nextafter(-1,0) f32
    float v = fmaxf(LO, __fadd_rn(__fmul_rn(u, 2.0f), LO));
    return __uint_as_float(0x3FB504F3u) * erfinvf(v);
}

// ---------------------------------------------------------------------------
// Single fused streaming kernel: 16 contiguous floats (4x float4) per thread
// (the R3-proven tile size: regs≈32, occ≈78%). Each 256-thread block lies
// entirely within one image; thread 0 computes the erase rectangle, threads
// 0-2 the per-channel inv/bias, shared through smem behind one bar.sync.
// ---------------------------------------------------------------------------
__global__ void __launch_bounds__(BLK)
erase_kernel(const float4* __restrict__ x,
             const float* __restrict__ mean,
             const float* __restrict__ stdv,
             float4* __restrict__ out) {
    __shared__ int4  s_rect;
    __shared__ float s_inv[CC];
    __shared__ float s_bias[CC];

    int t = blockIdx.x * BLK + threadIdx.x;      // chunk id, < NCH
    int b = blockIdx.x / BLOCKS_PER_IMG;         // image id (uniform per block)

    if (threadIdx.x == 0) s_rect = compute_rect(b);
    if (threadIdx.x < CC) {
        float inv = 1.0f / stdv[threadIdx.x];
        s_inv[threadIdx.x]  = inv;
        s_bias[threadIdx.x] = -mean[threadIdx.x] * inv;
    }

    // decode chunk -> (c, h, w0) once per thread (b already known)
    int r0 = t - b * CPI;
    int c  = r0 / CPC;
    int r1 = r0 - c * CPC;
    int h  = r1 / CPR;
    int w0 = (r1 - h * CPR) << 4;                // starting w of this chunk

    // front-batch the 4 vector loads for MLP=4
    alignas(16) float o[16];
    float4* ov4 = reinterpret_cast<float4*>(o);
    const float4* xp = x + (size_t)t * 4;
    ov4[0] = xp[0];
    ov4[1] = xp[1];
    ov4[2] = xp[2];
    ov4[3] = xp[3];

    __syncthreads();                             // s_rect / s_inv / s_bias ready
    float inv  = s_inv[c];
    float bias = s_bias[c];

    #pragma unroll
    for (int j = 0; j < 16; ++j)
        o[j] = fmaf(o[j], inv, bias);

    int4 rc = s_rect;
    // row-range + column-overlap test once per thread; rare path per-lane
    if (h >= rc.x && h < rc.y && w0 + 15 >= rc.z && w0 < rc.w) {
        unsigned i0 = (unsigned)t * 16u;         // global element index
        #pragma unroll
        for (int j = 0; j < 16; ++j) {
            int w = w0 + j;
            if (w >= rc.z && w < rc.w) o[j] = noise_at(i0 + (unsigned)j);
        }
    }

    float4* op = out + (size_t)t * 4;
    op[0] = ov4[0];
    op[1] = ov4[1];
    op[2] = ov4[2];
    op[3] = ov4[3];
}

// ---------------------------------------------------------------------------
// Launch
// ---------------------------------------------------------------------------
extern "C" void kernel_launch(void* const* d_in, const int* in_sizes, int n_in,
                              void* d_out, int out_size) {
    const float4* x   = (const float4*)d_in[0];
    const float*  mn  = (const float*)d_in[1];
    const float*  sd  = (const float*)d_in[2];
    float4*       out = (float4*)d_out;

    erase_kernel<<<NBLK, BLK>>>(x, mn, sd, out);
}